// round 17
// baseline (speedup 1.0000x reference)
#include <cuda_runtime.h>
#include <cuda_bf16.h>
#include <math.h>
#include <stdint.h>

#define Bn 32
#define Ln 32
#define NCc 528
#define Dd 384
#define MAXP 32768
#define WELEM (384*384)

// ---------------- device scratch (static, allocation-rule-safe) ----------------
__device__ float g_A [(size_t)Bn*NCc*Dd];
__device__ float g_Bb[(size_t)Bn*NCc*Dd];
__device__ float g_Cm[(size_t)Bn*NCc*Dd];
__device__ float g_H [(size_t)Bn*Ln*Dd];   // leaf temp only now
__device__ float g_X [(size_t)MAXP*Dd];
__device__ float g_P [MAXP];
// 9 weight matrices, each as EXACT 3-way bf16 split (h,m,l) in [n][k] layout
__device__ __nv_bfloat16 g_Wb[(size_t)9*3*WELEM];

__host__ __device__ __forceinline__ int offi(int l){ return l*Ln - (l*(l-1))/2; }

__device__ __forceinline__ float sigma_h_f(float x){
    float s = 1.f/(1.f+expf(-x));
    return x * tanhf(sqrtf(s));
}

__device__ __forceinline__ void in_idx(int level,int pos,int n,int&li,int&ri){
    li = offi(n) + pos;
    ri = offi(level-n-1) + pos + n + 1;
}
__device__ __forceinline__ void out_idx(int level,int pos,int n,int&par,int&sib){
    int T1 = Ln - pos - level - 1;
    if (n < T1){ par = offi(level+n+1)+pos;     sib = offi(n)+pos+level+1; }
    else { int s = n - T1; par = offi(level+s+1)+pos-s-1; sib = offi(s)+pos-s-1; }
}

// EXACT 3-way bf16 split of two fp32 values (packed bf16x2 each)
__device__ __forceinline__ void cvt3(float x0, float x1, uint32_t& h, uint32_t& m, uint32_t& l){
    asm("cvt.rn.bf16x2.f32 %0, %1, %2;" : "=r"(h) : "f"(x1), "f"(x0));
    float h0 = __uint_as_float(h << 16);
    float h1 = __uint_as_float(h & 0xffff0000u);
    float r0 = x0 - h0, r1 = x1 - h1;
    asm("cvt.rn.bf16x2.f32 %0, %1, %2;" : "=r"(m) : "f"(r1), "f"(r0));
    float m0 = __uint_as_float(m << 16);
    float m1 = __uint_as_float(m & 0xffff0000u);
    float s0 = r0 - m0, s1 = r1 - m1;
    asm("cvt.rn.bf16x2.f32 %0, %1, %2;" : "=r"(l) : "f"(s1), "f"(s0));
}

__device__ __forceinline__ void mma_bf16(float* c, const uint32_t* a, const uint32_t* b){
    asm("mma.sync.aligned.m16n8k16.row.col.f32.bf16.bf16.f32 "
        "{%0,%1,%2,%3}, {%4,%5,%6,%7}, {%8,%9}, {%0,%1,%2,%3};"
        : "+f"(c[0]), "+f"(c[1]), "+f"(c[2]), "+f"(c[3])
        : "r"(a[0]), "r"(a[1]), "r"(a[2]), "r"(a[3]), "r"(b[0]), "r"(b[1]));
}

// 128-thread block reduce of (sum, sumsq)
__device__ __forceinline__ void blockReduce2_128(float& s, float& q){
    __shared__ float shm[8];
    #pragma unroll
    for (int o=16;o>0;o>>=1){
        s += __shfl_xor_sync(0xffffffffu, s, o);
        q += __shfl_xor_sync(0xffffffffu, q, o);
    }
    int w = threadIdx.x>>5;
    if ((threadIdx.x&31)==0){ shm[w]=s; shm[4+w]=q; }
    __syncthreads();
    s = shm[0]+shm[1]+shm[2]+shm[3];
    q = shm[4]+shm[5]+shm[6]+shm[7];
    __syncthreads();
}

// ---------------- weight split: W[k][n] fp32 -> [n][k] bf16 h/m/l (exact) ----------------
struct WP { const float* W[9]; };

__global__ void __launch_bounds__(256) convw_k(WP wp, __nv_bfloat16* out){
    int mtx = blockIdx.y;
    int idx = blockIdx.x*256 + threadIdx.x;   // idx = n*384 + k
    int n = idx / Dd, k = idx - n*Dd;
    float x = wp.W[mtx][(size_t)k*Dd + n];
    __nv_bfloat16 h = __float2bfloat16(x);
    float r = x - __bfloat162float(h);
    __nv_bfloat16 m = __float2bfloat16(r);
    float s = r - __bfloat162float(m);
    __nv_bfloat16 l = __float2bfloat16(s);
    size_t base = (size_t)mtx*3*WELEM;
    out[base + idx]           = h;
    out[base + WELEM + idx]   = m;
    out[base + 2*WELEM + idx] = l;
}

// ---------------- bf16x8 exact-split TC GEMM, 64x128 tile ------------------------------
// K=32 chunks x 12, double-buffered smem (ONE sync/chunk), optional fused pair-compose.
// pairmode: 0 = plain gather (row r: b=r/pls, cell p=r-b*pls via bstride/cellOff)
//           1 = inside compose  A-row = sigma_h(Abase[li]+B2[ri]+b0)
//           2 = outside compose A-row = sigma_h(Abase[par]+B2[sib]+b0)
// In pairmode!=0 output mapping is dense (row r -> C + r*Dd).
struct GM { const __nv_bfloat16* Wh[3]; const __nv_bfloat16* Wm[3]; const __nv_bfloat16* Wl[3]; float* C[3]; };

#define KST 40                      // smem row stride in bf16 (32 k + 8 pad)
#define A_SPL (64*KST)              // 2560 bf16 per A split
#define B_SPL (128*KST)             // 5120 bf16 per B split
#define STAGE (3*A_SPL + 3*B_SPL)   // 23040 bf16 per stage
#define SMEM_GEMM_B (2*STAGE*2)     // 92160 bytes

__global__ void __launch_bounds__(256) gemm_k(
    const float* __restrict__ Abase, const float* __restrict__ B2,
    const float* __restrict__ b0c, GM gm, const float* __restrict__ bias,
    int rows, int pls, int bstride, int cellOff, int epi,
    int pairmode, int level, int nC)
{
    extern __shared__ __nv_bfloat16 ds[];
    const __nv_bfloat16* __restrict__ Wh = gm.Wh[blockIdx.z];
    const __nv_bfloat16* __restrict__ Wm = gm.Wm[blockIdx.z];
    const __nv_bfloat16* __restrict__ Wl = gm.Wl[blockIdx.z];
    float* __restrict__ Cb = gm.C[blockIdx.z];

    const int tid = threadIdx.x;
    const int bm = blockIdx.x<<6, bn = blockIdx.y<<7;

    // ---- A loader: 256 threads -> row tid>>2 (64 rows), quarter q=tid&3 (8 floats) ----
    const int arow = tid>>2, q = tid&3;
    const float *Ap = nullptr, *Ap2 = nullptr, *b0p = nullptr;
    {
        int r = bm + arow;
        if (r < rows){
            if (pairmode == 0){
                int b = r/pls, p = r - b*pls;
                Ap = Abase + (size_t)(b*bstride + cellOff + p)*Dd + q*8;
            } else {
                int bp = r/nC, n = r - bp*nC;
                int b = bp/pls, pos = bp - b*pls;
                int ia, ib;
                if (pairmode == 1) in_idx(level, pos, n, ia, ib);
                else               out_idx(level, pos, n, ia, ib);
                Ap  = Abase + (size_t)(b*NCc+ia)*Dd + q*8;
                Ap2 = B2    + (size_t)(b*NCc+ib)*Dd + q*8;
                b0p = b0c + q*8;
            }
        }
    }
    // ---- B loader: 256 threads -> row tid>>1 (128 rows), k-half (tid&1)*16 ----
    const int brow = tid>>1, bk = (tid&1)<<4;
    const __nv_bfloat16* Bph = Wh + (size_t)(bn + brow)*Dd + bk;
    const __nv_bfloat16* Bpm = Wm + (size_t)(bn + brow)*Dd + bk;
    const __nv_bfloat16* Bpl = Wl + (size_t)(bn + brow)*Dd + bk;

    float Cr[2][4][4], Cd[2][4][4];
    #pragma unroll
    for (int i=0;i<2;i++)
        #pragma unroll
        for (int j=0;j<4;j++)
            #pragma unroll
            for (int p=0;p<4;p++){ Cr[i][j][p]=0.f; Cd[i][j][p]=0.f; }

    const int wid = tid>>5, lane = tid&31;
    const int wm = (wid>>2)<<5;          // 0 or 32
    const int wn = (wid&3)<<5;           // 0,32,64,96
    const int g = lane>>2, tg = lane&3;

    // register prefetch buffers
    float va[8];
    uint4 pb[3][2];

    // load chunk k0 of A operand (with optional fused compose)
    auto loadA = [&](int k0){
        if (Ap){
            float4 x0 = *(const float4*)(Ap + k0);
            float4 x1 = *(const float4*)(Ap + k0 + 4);
            if (pairmode){
                float4 y0 = *(const float4*)(Ap2 + k0);
                float4 y1 = *(const float4*)(Ap2 + k0 + 4);
                float4 c0 = *(const float4*)(b0p + k0);
                float4 c1 = *(const float4*)(b0p + k0 + 4);
                va[0]=sigma_h_f(x0.x+y0.x+c0.x); va[1]=sigma_h_f(x0.y+y0.y+c0.y);
                va[2]=sigma_h_f(x0.z+y0.z+c0.z); va[3]=sigma_h_f(x0.w+y0.w+c0.w);
                va[4]=sigma_h_f(x1.x+y1.x+c1.x); va[5]=sigma_h_f(x1.y+y1.y+c1.y);
                va[6]=sigma_h_f(x1.z+y1.z+c1.z); va[7]=sigma_h_f(x1.w+y1.w+c1.w);
            } else {
                va[0]=x0.x; va[1]=x0.y; va[2]=x0.z; va[3]=x0.w;
                va[4]=x1.x; va[5]=x1.y; va[6]=x1.z; va[7]=x1.w;
            }
        } else {
            #pragma unroll
            for (int i=0;i<8;i++) va[i]=0.f;
        }
    };
    auto loadB = [&](int k0){
        pb[0][0] = *(const uint4*)(Bph + k0); pb[0][1] = *(const uint4*)(Bph + k0 + 8);
        pb[1][0] = *(const uint4*)(Bpm + k0); pb[1][1] = *(const uint4*)(Bpm + k0 + 8);
        pb[2][0] = *(const uint4*)(Bpl + k0); pb[2][1] = *(const uint4*)(Bpl + k0 + 8);
    };

    // prologue: chunk 0 into registers
    loadA(0); loadB(0);

    for (int c = 0; c < 12; c++){
        __nv_bfloat16* st = ds + (c & 1)*STAGE;
        // ---- commit staged registers to smem buffer c&1 ----
        {
            uint32_t h0,m0,l0,h1,m1,l1,h2,m2,l2,h3,m3,l3;
            cvt3(va[0], va[1], h0, m0, l0);
            cvt3(va[2], va[3], h1, m1, l1);
            cvt3(va[4], va[5], h2, m2, l2);
            cvt3(va[6], va[7], h3, m3, l3);
            int ao = arow*KST + q*8;
            *(uint4*)&st[ao]           = make_uint4(h0,h1,h2,h3);
            *(uint4*)&st[A_SPL + ao]   = make_uint4(m0,m1,m2,m3);
            *(uint4*)&st[2*A_SPL + ao] = make_uint4(l0,l1,l2,l3);
            int bo = 3*A_SPL + brow*KST + bk;
            *(uint4*)&st[bo]             = pb[0][0]; *(uint4*)&st[bo+8]           = pb[0][1];
            *(uint4*)&st[B_SPL + bo]     = pb[1][0]; *(uint4*)&st[B_SPL + bo+8]   = pb[1][1];
            *(uint4*)&st[2*B_SPL + bo]   = pb[2][0]; *(uint4*)&st[2*B_SPL + bo+8] = pb[2][1];
        }
        __syncthreads();

        // ---- prefetch next chunk globals (hidden under MMAs) ----
        if (c < 11){ loadA((c+1)*32); loadB((c+1)*32); }

        const __nv_bfloat16* Ash = st;
        const __nv_bfloat16* Asm = st + A_SPL;
        const __nv_bfloat16* Asl = st + 2*A_SPL;
        const __nv_bfloat16* Bsh = st + 3*A_SPL;
        const __nv_bfloat16* Bsm = Bsh + B_SPL;
        const __nv_bfloat16* Bsl = Bsh + 2*B_SPL;

        // two k16 groups (identical order to R13's chunks 2c, 2c+1 -> bit-identical)
        #pragma unroll
        for (int kk = 0; kk < 32; kk += 16){
            uint32_t Bh[4][2], Bm2[4][2], Bl[4][2];
            #pragma unroll
            for (int ni=0;ni<4;ni++){
                int c0 = (wn + ni*8 + g)*KST + kk + tg*2;
                Bh[ni][0]  = *(const uint32_t*)&Bsh[c0];
                Bh[ni][1]  = *(const uint32_t*)&Bsh[c0 + 8];
                Bm2[ni][0] = *(const uint32_t*)&Bsm[c0];
                Bm2[ni][1] = *(const uint32_t*)&Bsm[c0 + 8];
                Bl[ni][0]  = *(const uint32_t*)&Bsl[c0];
                Bl[ni][1]  = *(const uint32_t*)&Bsl[c0 + 8];
            }
            #pragma unroll
            for (int mi=0;mi<2;mi++){
                int r0 = (wm + mi*16 + g)*KST + kk + tg*2;
                uint32_t Ah[4], Am[4], Al[4];
                Ah[0] = *(const uint32_t*)&Ash[r0];
                Ah[1] = *(const uint32_t*)&Ash[r0 + 8*KST];
                Ah[2] = *(const uint32_t*)&Ash[r0 + 8];
                Ah[3] = *(const uint32_t*)&Ash[r0 + 8*KST + 8];
                Am[0] = *(const uint32_t*)&Asm[r0];
                Am[1] = *(const uint32_t*)&Asm[r0 + 8*KST];
                Am[2] = *(const uint32_t*)&Asm[r0 + 8];
                Am[3] = *(const uint32_t*)&Asm[r0 + 8*KST + 8];
                Al[0] = *(const uint32_t*)&Asl[r0];
                Al[1] = *(const uint32_t*)&Asl[r0 + 8*KST];
                Al[2] = *(const uint32_t*)&Asl[r0 + 8];
                Al[3] = *(const uint32_t*)&Asl[r0 + 8*KST + 8];

                #pragma unroll
                for (int ni=0;ni<4;ni++) mma_bf16(Cr[mi][ni], Ah, Bh[ni]);
                #pragma unroll
                for (int ni=0;ni<4;ni++) mma_bf16(Cd[mi][ni], Ah, Bm2[ni]);
                #pragma unroll
                for (int ni=0;ni<4;ni++) mma_bf16(Cd[mi][ni], Am, Bh[ni]);
                #pragma unroll
                for (int ni=0;ni<4;ni++) mma_bf16(Cd[mi][ni], Am, Bm2[ni]);
                #pragma unroll
                for (int ni=0;ni<4;ni++) mma_bf16(Cd[mi][ni], Ah, Bl[ni]);
                #pragma unroll
                for (int ni=0;ni<4;ni++) mma_bf16(Cd[mi][ni], Al, Bh[ni]);
                #pragma unroll
                for (int ni=0;ni<4;ni++) mma_bf16(Cd[mi][ni], Am, Bl[ni]);
                #pragma unroll
                for (int ni=0;ni<4;ni++) mma_bf16(Cd[mi][ni], Al, Bm2[ni]);
            }
        }
        // no trailing sync: next iteration writes the OTHER buffer; the top-of-loop
        // sync (after all threads finished this buffer's MMAs) protects reuse.
    }

    // ---- epilogue: single merge add per element ----
    #pragma unroll
    for (int mi=0;mi<2;mi++){
        #pragma unroll
        for (int half=0; half<2; half++){
            int r = bm + wm + mi*16 + g + half*8;
            if (r < rows){
                float* Crow;
                if (pairmode) Crow = Cb + (size_t)r*Dd + bn + wn;
                else { int b = r/pls, p = r - b*pls;
                       Crow = Cb + (size_t)(b*bstride + cellOff + p)*Dd + bn + wn; }
                #pragma unroll
                for (int ni=0;ni<4;ni++){
                    int c0 = ni*8 + tg*2;
                    float v0 = Cr[mi][ni][half*2+0] + Cd[mi][ni][half*2+0];
                    float v1 = Cr[mi][ni][half*2+1] + Cd[mi][ni][half*2+1];
                    if (epi){
                        v0 = sigma_h_f(v0 + bias[bn+wn+c0]);
                        v1 = sigma_h_f(v1 + bias[bn+wn+c0+1]);
                    }
                    *(float2*)(Crow + c0) = make_float2(v0, v1);
                }
            }
        }
    }
}

// ---------------- score + softmax kernels ----------------
__global__ void __launch_bounds__(256) score_in_k(
    const float* __restrict__ ih, float* __restrict__ isb,
    const float* __restrict__ cM, float* __restrict__ P, int level)
{
    int Ls = Ln - level;
    int bp = blockIdx.x;
    int b = bp / Ls, pos = bp - b*Ls;
    int warp = threadIdx.x >> 5, lane = threadIdx.x & 31;
    __shared__ float sc[32];
    for (int n = warp; n < level; n += 8){
        int li, ri; in_idx(level, pos, n, li, ri);
        const float* u = cM + (size_t)(b*NCc + li)*Dd;
        const float* v = ih + (size_t)(b*NCc + ri)*Dd;
        float s = 0.f;
        #pragma unroll 4
        for (int d = lane; d < Dd; d += 32) s += u[d]*v[d];
        #pragma unroll
        for (int o=16;o>0;o>>=1) s += __shfl_xor_sync(0xffffffffu, s, o);
        if (lane==0) sc[n] = s + isb[b*NCc+li] + isb[b*NCc+ri];
    }
    __syncthreads();
    if (warp==0){
        float v = (lane < level) ? sc[lane] : -1e30f;
        float m = v;
        #pragma unroll
        for (int o=16;o>0;o>>=1) m = fmaxf(m, __shfl_xor_sync(0xffffffffu, m, o));
        float e = (lane < level) ? expf(v - m) : 0.f;
        float se = e;
        #pragma unroll
        for (int o=16;o>0;o>>=1) se += __shfl_xor_sync(0xffffffffu, se, o);
        float p = e / se;
        float pb = (lane < level) ? p * v : 0.f;
        #pragma unroll
        for (int o=16;o>0;o>>=1) pb += __shfl_xor_sync(0xffffffffu, pb, o);
        if (lane < level) P[(size_t)bp*level + lane] = p;
        if (lane==0) isb[b*NCc + offi(level) + pos] = pb;
    }
}

__global__ void __launch_bounds__(256) score_out_k(
    const float* __restrict__ oh, float* __restrict__ osb,
    const float* __restrict__ isb, const float* __restrict__ cM,
    float* __restrict__ P, int level)
{
    int Ls = Ln - level, N = Ln - level - 1;
    int bp = blockIdx.x;
    int b = bp / Ls, pos = bp - b*Ls;
    int warp = threadIdx.x >> 5, lane = threadIdx.x & 31;
    __shared__ float sc[32];
    for (int n = warp; n < N; n += 8){
        int par, sib; out_idx(level, pos, n, par, sib);
        const float* u = cM + (size_t)(b*NCc + sib)*Dd;
        const float* v = oh + (size_t)(b*NCc + par)*Dd;
        float s = 0.f;
        #pragma unroll 4
        for (int d = lane; d < Dd; d += 32) s += u[d]*v[d];
        #pragma unroll
        for (int o=16;o>0;o>>=1) s += __shfl_xor_sync(0xffffffffu, s, o);
        if (lane==0) sc[n] = s + isb[b*NCc+sib] + osb[b*NCc+par];
    }
    __syncthreads();
    if (warp==0){
        float v = (lane < N) ? sc[lane] : -1e30f;
        float m = v;
        #pragma unroll
        for (int o=16;o>0;o>>=1) m = fmaxf(m, __shfl_xor_sync(0xffffffffu, m, o));
        float e = (lane < N) ? expf(v - m) : 0.f;
        float se = e;
        #pragma unroll
        for (int o=16;o>0;o>>=1) se += __shfl_xor_sync(0xffffffffu, se, o);
        float p = e / se;
        float pb = (lane < N) ? p * v : 0.f;
        #pragma unroll
        for (int o=16;o>0;o>>=1) pb += __shfl_xor_sync(0xffffffffu, pb, o);
        if (lane < N) P[(size_t)bp*N + lane] = p;
        if (lane==0) osb[b*NCc + offi(level) + pos] = pb;
    }
}

// ---------------- p-weighted sum over candidates + layer_norm ----------------
__global__ void __launch_bounds__(128) reduceln_k(
    const float* __restrict__ XC, const float* __restrict__ P,
    const float* __restrict__ gamma, const float* __restrict__ beta,
    float* __restrict__ out, int nC, int Ls, int cellOff)
{
    int bp = blockIdx.x;
    int b = bp / Ls, pos = bp - b*Ls;
    int t = threadIdx.x;
    float a0=0.f, a1=0.f, a2=0.f;
    const float* xrow = XC + (size_t)bp*nC*Dd;
    for (int n=0;n<nC;n++){
        float p = P[(size_t)bp*nC + n];
        const float* x = xrow + (size_t)n*Dd;
        a0 += p*x[t]; a1 += p*x[t+128]; a2 += p*x[t+256];
    }
    float s = a0+a1+a2;
    float q = a0*a0+a1*a1+a2*a2;
    blockReduce2_128(s, q);
    float mu = s * (1.f/384.f);
    float var = q * (1.f/384.f) - mu*mu;
    float r = rsqrtf(var + 1e-5f);
    float* o = out + (size_t)(b*NCc + cellOff + pos)*Dd;
    o[t]     = (a0-mu)*r*gamma[t]     + beta[t];
    o[t+128] = (a1-mu)*r*gamma[t+128] + beta[t+128];
    o[t+256] = (a2-mu)*r*gamma[t+256] + beta[t+256];
}

// ---------------- leaf: sigma_h(pre + leaf_b) -> layer_norm -> ih; zero is_ ----------------
__global__ void __launch_bounds__(128) leaf_k(
    const float* __restrict__ pre, const float* __restrict__ lb,
    const float* __restrict__ gamma, const float* __restrict__ beta,
    float* __restrict__ ih, float* __restrict__ isb)
{
    int row = blockIdx.x;
    int b = row >> 5, pos = row & 31;
    int t = threadIdx.x;
    const float* pr = pre + (size_t)row*Dd;
    float a0 = sigma_h_f(pr[t]     + lb[t]);
    float a1 = sigma_h_f(pr[t+128] + lb[t+128]);
    float a2 = sigma_h_f(pr[t+256] + lb[t+256]);
    float s = a0+a1+a2, q = a0*a0+a1*a1+a2*a2;
    blockReduce2_128(s, q);
    float mu = s * (1.f/384.f);
    float var = q * (1.f/384.f) - mu*mu;
    float r = rsqrtf(var + 1e-5f);
    float* o = ih + (size_t)(b*NCc + pos)*Dd;
    o[t]     = (a0-mu)*r*gamma[t]     + beta[t];
    o[t+128] = (a1-mu)*r*gamma[t+128] + beta[t+128];
    o[t+256] = (a2-mu)*r*gamma[t+256] + beta[t+256];
    if (t==0) isb[b*NCc + pos] = 0.f;
}

// ---------------- root: oh[:, -1] = layer_norm(root_h); os[:, -1] = 0 ----------------
__global__ void __launch_bounds__(128) root_k(
    const float* __restrict__ rh,
    const float* __restrict__ gamma, const float* __restrict__ beta,
    float* __restrict__ oh, float* __restrict__ osb)
{
    int b = blockIdx.x;
    int t = threadIdx.x;
    float a0 = rh[t], a1 = rh[t+128], a2 = rh[t+256];
    float s = a0+a1+a2, q = a0*a0+a1*a1+a2*a2;
    blockReduce2_128(s, q);
    float mu = s * (1.f/384.f);
    float var = q * (1.f/384.f) - mu*mu;
    float r = rsqrtf(var + 1e-5f);
    float* o = oh + (size_t)(b*NCc + NCc-1)*Dd;
    o[t]     = (a0-mu)*r*gamma[t]     + beta[t];
    o[t+128] = (a1-mu)*r*gamma[t+128] + beta[t+128];
    o[t+256] = (a2-mu)*r*gamma[t+256] + beta[t+256];
    if (t==0) osb[b*NCc + NCc-1] = 0.f;
}

// ---------------- orchestration ----------------
extern "C" void kernel_launch(void* const* d_in, const int* in_sizes, int n_in,
                              void* d_out, int out_size)
{
    (void)in_sizes; (void)n_in; (void)out_size;
    const float* x        = (const float*)d_in[0];
    const float* leaf_W   = (const float*)d_in[1];
    const float* leaf_b   = (const float*)d_in[2];
    const float* in_ln_g  = (const float*)d_in[3];
    const float* in_ln_b  = (const float*)d_in[4];
    const float* out_ln_g = (const float*)d_in[5];
    const float* out_ln_b = (const float*)d_in[6];
    const float* root_h   = (const float*)d_in[7];
    const float* in_bi    = (const float*)d_in[8];
    const float* out_bi   = (const float*)d_in[9];
    const float* in_W0    = (const float*)d_in[10];
    const float* in_W1    = (const float*)d_in[11];
    const float* in_B0    = (const float*)d_in[12];
    const float* in_W2    = (const float*)d_in[13];
    const float* in_B1    = (const float*)d_in[14];
    const float* out_W0   = (const float*)d_in[15];
    const float* out_W1   = (const float*)d_in[16];
    const float* out_B0   = (const float*)d_in[17];
    const float* out_W2   = (const float*)d_in[18];
    const float* out_B1   = (const float*)d_in[19];

    float* ih  = (float*)d_out;
    float* isb = ih  + (size_t)Bn*NCc*Dd;
    float* oh  = isb + (size_t)Bn*NCc;
    float* osb = oh  + (size_t)Bn*NCc*Dd;

    float *A,*Bb,*Cm,*H,*X,*P; __nv_bfloat16* Wb;
    cudaGetSymbolAddress((void**)&A,  g_A);
    cudaGetSymbolAddress((void**)&Bb, g_Bb);
    cudaGetSymbolAddress((void**)&Cm, g_Cm);
    cudaGetSymbolAddress((void**)&H,  g_H);
    cudaGetSymbolAddress((void**)&X,  g_X);
    cudaGetSymbolAddress((void**)&P,  g_P);
    cudaGetSymbolAddress((void**)&Wb, g_Wb);

    cudaFuncSetAttribute(gemm_k, cudaFuncAttributeMaxDynamicSharedMemorySize, SMEM_GEMM_B);

    auto WH = [&](int m){ return (const __nv_bfloat16*)(Wb + (size_t)m*3*WELEM); };
    auto WM = [&](int m){ return (const __nv_bfloat16*)(Wb + (size_t)m*3*WELEM + WELEM); };
    auto WL = [&](int m){ return (const __nv_bfloat16*)(Wb + (size_t)m*3*WELEM + 2*WELEM); };

    {
        WP wp;
        wp.W[0]=leaf_W; wp.W[1]=in_W0; wp.W[2]=in_W1; wp.W[3]=in_bi; wp.W[4]=in_W2;
        wp.W[5]=out_W0; wp.W[6]=out_W1; wp.W[7]=out_bi; wp.W[8]=out_W2;
        convw_k<<<dim3(WELEM/256,9),256>>>(wp, Wb);
    }

    auto setg = [&](GM& g, int slot, int m, float* C){
        g.Wh[slot]=WH(m); g.Wm[slot]=WM(m); g.Wl[slot]=WL(m); g.C[slot]=C;
    };

    // ---- leaf level ----
    {
        GM gm; setg(gm,0,0,H); setg(gm,1,0,H); setg(gm,2,0,H);
        gemm_k<<<dim3(16,3,1),256,SMEM_GEMM_B>>>(x, nullptr, nullptr, gm, nullptr,
            Bn*Ln, Bn*Ln, 0, 0, 0, 0, 0, 1);
        leaf_k<<<Bn*Ln,128>>>(H, leaf_b, in_ln_g, in_ln_b, ih, isb);
        GM g3; setg(g3,0,1,A); setg(g3,1,2,Bb); setg(g3,2,3,Cm);
        gemm_k<<<dim3(16,3,3),256,SMEM_GEMM_B>>>(ih, nullptr, nullptr, g3, nullptr,
            Bn*Ln, Ln, NCc, 0, 0, 0, 0, 1);
    }

    // ---- inside pass ----
    for (int level=1; level<Ln; level++){
        int Ls = Ln-level, nC = level;
        int rowsBP = Bn*Ls, Pn = rowsBP*nC;
        score_in_k<<<rowsBP,256>>>(ih, isb, Cm, P, level);
        GM g1; setg(g1,0,4,X); setg(g1,1,4,X); setg(g1,2,4,X);
        gemm_k<<<dim3((Pn+63)/64,3,1),256,SMEM_GEMM_B>>>(A, Bb, in_B0, g1, in_B1,
            Pn, Ls, 0, 0, 1, 1, level, nC);
        reduceln_k<<<rowsBP,128>>>(X, P, in_ln_g, in_ln_b, ih, nC, Ls, offi(level));
        if (level < Ln-1){
            GM g3; setg(g3,0,1,A); setg(g3,1,2,Bb); setg(g3,2,3,Cm);
            gemm_k<<<dim3((rowsBP+63)/64,3,3),256,SMEM_GEMM_B>>>(ih, nullptr, nullptr, g3, nullptr,
                rowsBP, Ls, NCc, offi(level), 0, 0, 0, 1);
        }
    }

    // ---- outside prep: sib @ out_W1, sib @ out_bi for ALL inside cells ----
    {
        GM g2; setg(g2,0,6,Bb); setg(g2,1,7,Cm); setg(g2,2,7,Cm);
        gemm_k<<<dim3((Bn*NCc+63)/64,3,2),256,SMEM_GEMM_B>>>(ih, nullptr, nullptr, g2, nullptr,
            Bn*NCc, NCc, NCc, 0, 0, 0, 0, 1);
        root_k<<<Bn,128>>>(root_h, out_ln_g, out_ln_b, oh, osb);
        GM gr; setg(gr,0,5,A); setg(gr,1,5,A); setg(gr,2,5,A);
        gemm_k<<<dim3(1,3,1),256,SMEM_GEMM_B>>>(oh, nullptr, nullptr, gr, nullptr,
            Bn, 1, NCc, NCc-1, 0, 0, 0, 1);
    }

    // ---- outside pass ----
    for (int level=Ln-2; level>=0; level--){
        int Ls = Ln-level, nC = Ln-level-1;
        int rowsBP = Bn*Ls, Pn = rowsBP*nC;
        score_out_k<<<rowsBP,256>>>(oh, osb, isb, Cm, P, level);
        GM g1; setg(g1,0,8,X); setg(g1,1,8,X); setg(g1,2,8,X);
        gemm_k<<<dim3((Pn+63)/64,3,1),256,SMEM_GEMM_B>>>(A, Bb, out_B0, g1, out_B1,
            Pn, Ls, 0, 0, 1, 2, level, nC);
        reduceln_k<<<rowsBP,128>>>(X, P, out_ln_g, out_ln_b, oh, nC, Ls, offi(level));
        if (level > 0){
            GM g3; setg(g3,0,5,A); setg(g3,1,5,A); setg(g3,2,5,A);
            gemm_k<<<dim3((rowsBP+63)/64,3,1),256,SMEM_GEMM_B>>>(oh, nullptr, nullptr, g3, nullptr,
                rowsBP, Ls, NCc, offi(level), 0, 0, 0, 1);
        }
    }
}